// round 15
// baseline (speedup 1.0000x reference)
#include <cuda_runtime.h>

#define BB 16
#define TMAX 512
#define DD 512
#define T_FRAMES 4096   // TMAX * MAX_DUR(8)
#define RPB 16          // rows (frames) per block (2 groups x 8)
#define RPG 8           // rows per 128-thread group

// Single fused kernel. One block per RPB consecutive (b, frame) rows,
// 256 threads = two 128-thread row-groups sharing one ds-scan prologue.
// Body: batched row copy + one-hot map writes, streamed through L2 with
// evict-first policy (__stcs): keeps L2's coalesced write-drain path
// (write-through regressed 8us) without evicting the L2-resident xs.
__global__ void __launch_bounds__(256) fused_kernel(
    const float4* __restrict__ xs,   // [B, TMAX, D/4]
    const int*    __restrict__ ds,   // [B, TMAX] int32 (JAX x64 disabled)
    float4* __restrict__ ys,         // [B, T_FRAMES, D/4]
    float4* __restrict__ mp)         // [B, T_FRAMES, TMAX/4]
{
    const int row0 = blockIdx.x * RPB;        // first global row (b*T_FRAMES+f)
    const int b    = row0 >> 12;              // / T_FRAMES
    const int fl0  = row0 & (T_FRAMES - 1);   // LOCAL frame within batch b
    const int tid  = threadIdx.x;             // 0..255
    const int k    = tid & 127;               // column (float4) within row
    const int g    = tid >> 7;                // row-group 0/1
    const int lane = tid & 31;
    const int w    = tid >> 5;                // warp 0..7

    __shared__ int s_wsum[8];
    __shared__ int s_tok[RPB];

    // ---- Prologue: find covering token for local frames [fl0, fl0+RPB) ----
    // Each of 256 threads owns 2 consecutive tokens: 2*tid, 2*tid+1.
    const int2 dv = ((const int2*)(ds + b * TMAX))[tid];
    const int lsum = dv.x + dv.y;

    // inclusive warp scan of per-thread sums
    int v = lsum;
    #pragma unroll
    for (int off = 1; off < 32; off <<= 1) {
        int n = __shfl_up_sync(0xffffffffu, v, off);
        if (lane >= off) v += n;
    }
    const int laneExcl = v - lsum;
    if (lane == 31) s_wsum[w] = v;
    if (tid < RPB)  s_tok[tid] = -1;
    __syncthreads();

    // exclusive prefix across the 8 warps (branch-free)
    int wExcl = 0;
    #pragma unroll
    for (int j = 0; j < 7; j++)
        wExcl += (j < w) ? s_wsum[j] : 0;

    // walk this thread's 2 tokens; mark any of the block's frames they cover.
    // Intervals are disjoint -> at most one writer per s_tok slot.
    {
        int st = wExcl + laneExcl;
        const int dd2[2] = {dv.x, dv.y};
        #pragma unroll
        for (int c = 0; c < 2; c++) {
            const int en = st + dd2[c];
            #pragma unroll
            for (int j = 0; j < RPB; j++) {
                const int fl = fl0 + j;       // LOCAL frame index
                if (st <= fl && fl < en) s_tok[j] = 2 * tid + c;
            }
            st = en;
        }
    }
    __syncthreads();

    // ---- Body: this group handles rows row0 + g*RPG .. +RPG-1 ----
    const int rbase = row0 + g * RPG;         // global row base for this group

    int tok[RPG];
    #pragma unroll
    for (int j = 0; j < RPG; j++) tok[j] = s_tok[g * RPG + j];

    float4 yv[RPG];
    #pragma unroll
    for (int j = 0; j < RPG; j++) {
        yv[j] = make_float4(0.f, 0.f, 0.f, 0.f);
        if (tok[j] >= 0)
            yv[j] = xs[((size_t)b * TMAX + tok[j]) * (DD / 4) + k];
    }

    #pragma unroll
    for (int j = 0; j < RPG; j++)
        __stcs(&ys[(size_t)(rbase + j) * (DD / 4) + k], yv[j]);

    #pragma unroll
    for (int j = 0; j < RPG; j++) {
        float4 mv = make_float4(0.f, 0.f, 0.f, 0.f);
        if (tok[j] >= 0 && (tok[j] >> 2) == k)
            ((float*)&mv)[tok[j] & 3] = 1.0f;
        __stcs(&mp[(size_t)(rbase + j) * (TMAX / 4) + k], mv);
    }
}

extern "C" void kernel_launch(void* const* d_in, const int* in_sizes, int n_in,
                              void* d_out, int out_size) {
    const float* xs = (const float*)d_in[0];
    const int*   ds = (const int*)d_in[1];   // int32 (JAX x64 disabled)

    float* out = (float*)d_out;
    float* ys  = out;                                    // [B, T_FRAMES, D]
    float* mp  = out + (size_t)BB * T_FRAMES * DD;       // [B, T_FRAMES, TMAX]

    fused_kernel<<<(BB * T_FRAMES) / RPB, 256>>>(
        (const float4*)xs, ds, (float4*)ys, (float4*)mp);
}